// round 1
// baseline (speedup 1.0000x reference)
#include <cuda_runtime.h>
#include <cstdint>

#define F 128
#define F4 32
static const int NN1 = 50000;   // nodes in g
static const int NE1 = 400000;  // edges in g == nodes of line graph
static const int NE2 = 800000;  // edges in line graph
#define MAXN 400000
#define MAXE 800000

// ---------------- scratch (device globals: no cudaMalloc allowed) ----------
__device__ float  g_P0[(size_t)MAXN * F];
__device__ float  g_P1[(size_t)MAXN * F];
__device__ float  g_P3[(size_t)MAXN * F];
__device__ float  g_P4[(size_t)MAXN * F];
__device__ float  g_emsg[(size_t)MAXE * F];
__device__ float  g_h[(size_t)MAXN * F];
__device__ int    g_deg[MAXN];
__device__ int    g_starts[MAXN + 1];
__device__ int    g_cursor[MAXN];
__device__ int    g_elist[MAXE];
__device__ int    g_bsum[1024];
__device__ double g_statsE[256];  // [0:128) sum, [128:256) sumsq
__device__ double g_statsN[256];
__device__ float  g_scaleE[F], g_shiftE[F], g_scaleN[F], g_shiftN[F];

__device__ __forceinline__ float sigm(float v) { return 1.0f / (1.0f + __expf(-v)); }

// ---------------- fp32 GEMM: out[r][c] = sum_k A[r][k]*W[c][k] + b[c] -------
// A: [R,128] row-major, W: [128,128] row-major, K=N=128 fixed.
// Block = 128 rows x 128 cols, 256 threads, 8x8 register tile per thread.
__global__ void __launch_bounds__(256) gemm_nt_bias(
    const float* __restrict__ A, const float* __restrict__ W,
    const float* __restrict__ bias, float* __restrict__ out, int R)
{
    extern __shared__ float sm[];
    float* Wsh = sm;            // [128][128], Wsh[k*128+c] = W[c][k]
    float* As  = sm + 16384;    // [16][128],  As[t*128+r]  = A[row][kk+t]

    const int tid = threadIdx.x;
    const int tx = tid & 15, ty = tid >> 4;
    const long long rowBase = (long long)blockIdx.x * 128;

    // Load full W transposed into smem (coalesced along k)
    #pragma unroll
    for (int u = 0; u < 16; u++) {
        int idx = tid + u * 256;        // 0..4095 float4s of W
        int c  = idx >> 5;              // output feature
        int k4 = idx & 31;              // float4 along k
        float4 w = ((const float4*)W)[idx];
        Wsh[(k4 * 4 + 0) * 128 + c] = w.x;
        Wsh[(k4 * 4 + 1) * 128 + c] = w.y;
        Wsh[(k4 * 4 + 2) * 128 + c] = w.z;
        Wsh[(k4 * 4 + 3) * 128 + c] = w.w;
    }

    float acc[8][8];
    #pragma unroll
    for (int m = 0; m < 8; m++)
        #pragma unroll
        for (int n = 0; n < 8; n++) acc[m][n] = 0.f;

    const int r0 = ty * 4, c0 = tx * 4;

    for (int kk = 0; kk < 128; kk += 16) {
        __syncthreads();
        #pragma unroll
        for (int u = 0; u < 2; u++) {
            int idx = tid + u * 256;    // 0..511 float4s of the A tile
            int r = idx >> 2;
            int q = idx & 3;
            long long row = rowBase + r;
            float4 a = make_float4(0.f, 0.f, 0.f, 0.f);
            if (row < R) a = ((const float4*)(A + row * 128))[(kk >> 2) + q];
            As[(q * 4 + 0) * 128 + r] = a.x;
            As[(q * 4 + 1) * 128 + r] = a.y;
            As[(q * 4 + 2) * 128 + r] = a.z;
            As[(q * 4 + 3) * 128 + r] = a.w;
        }
        __syncthreads();
        #pragma unroll
        for (int t = 0; t < 16; t++) {
            float4 a0 = *(const float4*)&As[t * 128 + r0];
            float4 a1 = *(const float4*)&As[t * 128 + r0 + 64];
            float4 b0 = *(const float4*)&Wsh[(kk + t) * 128 + c0];
            float4 b1 = *(const float4*)&Wsh[(kk + t) * 128 + c0 + 64];
            float am[8] = {a0.x, a0.y, a0.z, a0.w, a1.x, a1.y, a1.z, a1.w};
            float bv[8] = {b0.x, b0.y, b0.z, b0.w, b1.x, b1.y, b1.z, b1.w};
            #pragma unroll
            for (int m = 0; m < 8; m++)
                #pragma unroll
                for (int n = 0; n < 8; n++)
                    acc[m][n] = fmaf(am[m], bv[n], acc[m][n]);
        }
    }

    float4 bb0 = ((const float4*)bias)[tx];
    float4 bb1 = ((const float4*)bias)[tx + 16];
    #pragma unroll
    for (int m = 0; m < 8; m++) {
        long long row = rowBase + r0 + (m < 4 ? m : 64 + (m - 4));
        if (row >= R) continue;
        float4 o0 = make_float4(acc[m][0] + bb0.x, acc[m][1] + bb0.y,
                                acc[m][2] + bb0.z, acc[m][3] + bb0.w);
        float4 o1 = make_float4(acc[m][4] + bb1.x, acc[m][5] + bb1.y,
                                acc[m][6] + bb1.z, acc[m][7] + bb1.w);
        ((float4*)(out + row * 128))[tx]      = o0;
        ((float4*)(out + row * 128))[tx + 16] = o1;
    }
}

// ---------------- CSR build ------------------------------------------------
__global__ void hist_deg(const int* __restrict__ ei, int* __restrict__ deg, int E)
{
    for (int e = blockIdx.x * blockDim.x + threadIdx.x; e < E;
         e += gridDim.x * blockDim.x)
        atomicAdd(&deg[ei[e]], 1);
}

__global__ void scan1(const int* __restrict__ in, int* __restrict__ out,
                      int* __restrict__ bsum, int n)
{
    __shared__ int s[1024];
    int i = blockIdx.x * 1024 + threadIdx.x;
    int v = (i < n) ? in[i] : 0;
    s[threadIdx.x] = v;
    __syncthreads();
    for (int off = 1; off < 1024; off <<= 1) {
        int t = (threadIdx.x >= off) ? s[threadIdx.x - off] : 0;
        __syncthreads();
        s[threadIdx.x] += t;
        __syncthreads();
    }
    if (i < n) out[i] = s[threadIdx.x] - v;      // exclusive
    if (threadIdx.x == 1023) bsum[blockIdx.x] = s[1023];
}

__global__ void scan2(int* __restrict__ bsum, int nb)
{
    __shared__ int s[1024];
    int v = (threadIdx.x < nb) ? bsum[threadIdx.x] : 0;
    s[threadIdx.x] = v;
    __syncthreads();
    for (int off = 1; off < 1024; off <<= 1) {
        int t = (threadIdx.x >= off) ? s[threadIdx.x - off] : 0;
        __syncthreads();
        s[threadIdx.x] += t;
        __syncthreads();
    }
    if (threadIdx.x < nb) bsum[threadIdx.x] = s[threadIdx.x] - v;  // exclusive
}

__global__ void scan3(int* __restrict__ out, const int* __restrict__ bsum,
                      int n, int total)
{
    int i = blockIdx.x * 1024 + threadIdx.x;
    if (i < n) out[i] += bsum[blockIdx.x];
    if (blockIdx.x == 0 && threadIdx.x == 0) out[n] = total;
}

__global__ void scatter_edges(const int* __restrict__ ei,
                              const int* __restrict__ starts,
                              int* __restrict__ cursor, int* __restrict__ elist, int E)
{
    for (int e = blockIdx.x * blockDim.x + threadIdx.x; e < E;
         e += gridDim.x * blockDim.x) {
        int n = ei[e];
        int p = atomicAdd(&cursor[n], 1);
        elist[starts[n] + p] = e;
    }
}

// ---------------- edge pass: emsg = P0[i] + P1[j] + (e@W2^T+b2), + BN stats -
// One warp per edge (lane owns 4 features).
__global__ void __launch_bounds__(256) edge_pass(
    const int* __restrict__ ei, const int* __restrict__ ej,
    const float* __restrict__ P0, const float* __restrict__ P1,
    float* __restrict__ emsg, int E, double* __restrict__ stats)
{
    __shared__ float ssum[128], ssq[128];
    if (threadIdx.x < 128) { ssum[threadIdx.x] = 0.f; ssq[threadIdx.x] = 0.f; }
    __syncthreads();
    const int lane = threadIdx.x & 31;
    float4 ls = make_float4(0.f, 0.f, 0.f, 0.f);
    float4 lq = make_float4(0.f, 0.f, 0.f, 0.f);
    const long long total = (long long)E * 32;
    for (long long idx = (long long)blockIdx.x * blockDim.x + threadIdx.x;
         idx < total; idx += (long long)gridDim.x * blockDim.x) {
        int e = (int)(idx >> 5);
        int i = ei[e], j = ej[e];
        float4 v  = ((const float4*)emsg)[idx];
        float4 p0 = ((const float4*)P0)[(long long)i * 32 + lane];
        float4 p1 = ((const float4*)P1)[(long long)j * 32 + lane];
        v.x += p0.x + p1.x; v.y += p0.y + p1.y;
        v.z += p0.z + p1.z; v.w += p0.w + p1.w;
        ((float4*)emsg)[idx] = v;
        ls.x += v.x; ls.y += v.y; ls.z += v.z; ls.w += v.w;
        lq.x += v.x * v.x; lq.y += v.y * v.y; lq.z += v.z * v.z; lq.w += v.w * v.w;
    }
    atomicAdd(&ssum[lane * 4 + 0], ls.x); atomicAdd(&ssum[lane * 4 + 1], ls.y);
    atomicAdd(&ssum[lane * 4 + 2], ls.z); atomicAdd(&ssum[lane * 4 + 3], ls.w);
    atomicAdd(&ssq[lane * 4 + 0], lq.x);  atomicAdd(&ssq[lane * 4 + 1], lq.y);
    atomicAdd(&ssq[lane * 4 + 2], lq.z);  atomicAdd(&ssq[lane * 4 + 3], lq.w);
    __syncthreads();
    if (threadIdx.x < 128) {
        atomicAdd(&stats[threadIdx.x],       (double)ssum[threadIdx.x]);
        atomicAdd(&stats[128 + threadIdx.x], (double)ssq[threadIdx.x]);
    }
}

// ---------------- per-node aggregation (warp per node, CSR gather) ---------
__global__ void __launch_bounds__(256) node_agg(
    const int* __restrict__ starts, const int* __restrict__ elist,
    const int* __restrict__ ej, const float* __restrict__ emsg,
    const float* __restrict__ P4, const float* __restrict__ P3,
    float* __restrict__ h, int nN, double* __restrict__ stats)
{
    __shared__ float ssum[128], ssq[128];
    if (threadIdx.x < 128) { ssum[threadIdx.x] = 0.f; ssq[threadIdx.x] = 0.f; }
    __syncthreads();
    const int lane  = threadIdx.x & 31;
    const int warp  = (blockIdx.x * blockDim.x + threadIdx.x) >> 5;
    const int nwarp = (gridDim.x * blockDim.x) >> 5;
    float4 ls = make_float4(0.f, 0.f, 0.f, 0.f);
    float4 lq = make_float4(0.f, 0.f, 0.f, 0.f);
    for (int n = warp; n < nN; n += nwarp) {
        int s = starts[n], t = starts[n + 1];
        float4 sg = make_float4(0.f, 0.f, 0.f, 0.f);
        float4 sn = make_float4(0.f, 0.f, 0.f, 0.f);
        for (int k = s; k < t; k++) {
            int e = elist[k];
            int j = ej[e];
            float4 v  = ((const float4*)emsg)[(long long)e * 32 + lane];
            float4 sig = make_float4(sigm(v.x), sigm(v.y), sigm(v.z), sigm(v.w));
            float4 p4 = ((const float4*)P4)[(long long)j * 32 + lane];
            sg.x += sig.x; sg.y += sig.y; sg.z += sig.z; sg.w += sig.w;
            sn.x += sig.x * p4.x; sn.y += sig.y * p4.y;
            sn.z += sig.z * p4.z; sn.w += sig.w * p4.w;
        }
        float4 hv = ((const float4*)P3)[(long long)n * 32 + lane];
        hv.x += sn.x / (sg.x + 1e-9f); hv.y += sn.y / (sg.y + 1e-9f);
        hv.z += sn.z / (sg.z + 1e-9f); hv.w += sn.w / (sg.w + 1e-9f);
        ((float4*)h)[(long long)n * 32 + lane] = hv;
        ls.x += hv.x; ls.y += hv.y; ls.z += hv.z; ls.w += hv.w;
        lq.x += hv.x * hv.x; lq.y += hv.y * hv.y;
        lq.z += hv.z * hv.z; lq.w += hv.w * hv.w;
    }
    atomicAdd(&ssum[lane * 4 + 0], ls.x); atomicAdd(&ssum[lane * 4 + 1], ls.y);
    atomicAdd(&ssum[lane * 4 + 2], ls.z); atomicAdd(&ssum[lane * 4 + 3], ls.w);
    atomicAdd(&ssq[lane * 4 + 0], lq.x);  atomicAdd(&ssq[lane * 4 + 1], lq.y);
    atomicAdd(&ssq[lane * 4 + 2], lq.z);  atomicAdd(&ssq[lane * 4 + 3], lq.w);
    __syncthreads();
    if (threadIdx.x < 128) {
        atomicAdd(&stats[threadIdx.x],       (double)ssum[threadIdx.x]);
        atomicAdd(&stats[128 + threadIdx.x], (double)ssq[threadIdx.x]);
    }
}

// ---------------- BN finalize + fused apply ---------------------------------
__global__ void finalize_bn(const double* __restrict__ stats,
                            const float* __restrict__ gamma,
                            const float* __restrict__ beta,
                            double invR, float* __restrict__ scale,
                            float* __restrict__ shift)
{
    int f = threadIdx.x;
    double mu  = stats[f] * invR;
    double var = stats[128 + f] * invR - mu * mu;
    float inv = rsqrtf((float)var + 1e-5f);
    float s = gamma[f] * inv;
    scale[f] = s;
    shift[f] = beta[f] - s * (float)mu;
}

__global__ void apply_bn_silu_res(const float* __restrict__ hbuf,
                                  const float* __restrict__ res,
                                  const float* __restrict__ scale,
                                  const float* __restrict__ shift,
                                  float* __restrict__ out, long long n4)
{
    for (long long idx = (long long)blockIdx.x * blockDim.x + threadIdx.x;
         idx < n4; idx += (long long)gridDim.x * blockDim.x) {
        int l = (int)(idx & 31);
        float4 sc = ((const float4*)scale)[l];
        float4 sh = ((const float4*)shift)[l];
        float4 v = ((const float4*)hbuf)[idx];
        v.x = v.x * sc.x + sh.x; v.y = v.y * sc.y + sh.y;
        v.z = v.z * sc.z + sh.z; v.w = v.w * sc.w + sh.w;
        float4 u = make_float4(v.x * sigm(v.x), v.y * sigm(v.y),
                               v.z * sigm(v.z), v.w * sigm(v.w));
        float4 r = ((const float4*)res)[idx];
        u.x += r.x; u.y += r.y; u.z += r.z; u.w += r.w;
        ((float4*)out)[idx] = u;
    }
}

// ---------------- host orchestration ----------------------------------------
struct Scratch {
    float *P0, *P1, *P3, *P4, *emsg, *h;
    int *deg, *starts, *cursor, *elist, *bsum;
    double *statsE, *statsN;
    float *scaleE, *shiftE, *scaleN, *shiftN;
};

static void run_conv(const Scratch& S,
                     const int* ei, const int* ej, int nN, int E,
                     const float* xnode, const float* eedge,
                     const float* W, const float* b,
                     const float* bng, const float* bnb,
                     const float* node_res, float* node_out,
                     const float* edge_res, float* edge_out)
{
    cudaStream_t st = 0;
    // zero accumulators
    cudaMemsetAsync(S.deg, 0, (size_t)nN * sizeof(int), st);
    cudaMemsetAsync(S.cursor, 0, (size_t)nN * sizeof(int), st);
    cudaMemsetAsync(S.statsE, 0, 256 * sizeof(double), st);
    cudaMemsetAsync(S.statsN, 0, 256 * sizeof(double), st);

    const size_t gsmem = (16384 + 2048) * sizeof(float);
    int gbN = (nN + 127) / 128;
    int gbE = (E + 127) / 128;
    // node-level GEMMs: P0=W[0], P1=W[1], P3=W[3], P4=W[4]
    gemm_nt_bias<<<gbN, 256, gsmem, st>>>(xnode, W + 0 * 16384, b + 0 * 128, S.P0, nN);
    gemm_nt_bias<<<gbN, 256, gsmem, st>>>(xnode, W + 1 * 16384, b + 1 * 128, S.P1, nN);
    gemm_nt_bias<<<gbN, 256, gsmem, st>>>(xnode, W + 3 * 16384, b + 3 * 128, S.P3, nN);
    gemm_nt_bias<<<gbN, 256, gsmem, st>>>(xnode, W + 4 * 16384, b + 4 * 128, S.P4, nN);
    // edge-level GEMM into emsg
    gemm_nt_bias<<<gbE, 256, gsmem, st>>>(eedge, W + 2 * 16384, b + 2 * 128, S.emsg, E);

    // CSR
    hist_deg<<<2048, 256, 0, st>>>(ei, S.deg, E);
    int nb = (nN + 1023) / 1024;
    scan1<<<nb, 1024, 0, st>>>(S.deg, S.starts, S.bsum, nN);
    scan2<<<1, 1024, 0, st>>>(S.bsum, nb);
    scan3<<<nb, 1024, 0, st>>>(S.starts, S.bsum, nN, E);
    scatter_edges<<<2048, 256, 0, st>>>(ei, S.starts, S.cursor, S.elist, E);

    // edge message + edge-BN stats
    edge_pass<<<4096, 256, 0, st>>>(ei, ej, S.P0, S.P1, S.emsg, E, S.statsE);
    finalize_bn<<<1, 128, 0, st>>>(S.statsE, bng + 0 * 128, bnb + 0 * 128,
                                   1.0 / (double)E, S.scaleE, S.shiftE);

    // node aggregation + node-BN stats
    node_agg<<<4096, 256, 0, st>>>(S.starts, S.elist, ej, S.emsg, S.P4, S.P3,
                                   S.h, nN, S.statsN);
    finalize_bn<<<1, 128, 0, st>>>(S.statsN, bng + 1 * 128, bnb + 1 * 128,
                                   1.0 / (double)nN, S.scaleN, S.shiftN);

    // fused BN + silu + residual
    long long n4n = (long long)nN * 32;
    long long n4e = (long long)E * 32;
    int gbA = (int)((n4n + 255) / 256); if (gbA > 8192) gbA = 8192;
    int gbB = (int)((n4e + 255) / 256); if (gbB > 8192) gbB = 8192;
    apply_bn_silu_res<<<gbA, 256, 0, st>>>(S.h, node_res, S.scaleN, S.shiftN,
                                           node_out, n4n);
    apply_bn_silu_res<<<gbB, 256, 0, st>>>(S.emsg, edge_res, S.scaleE, S.shiftE,
                                           edge_out, n4e);
}

extern "C" void kernel_launch(void* const* d_in, const int* in_sizes, int n_in,
                              void* d_out, int out_size)
{
    const int*   gidx = (const int*)d_in[0];      // [2, NE1]
    const int*   lidx = (const int*)d_in[1];      // [2, NE2]
    const float* x    = (const float*)d_in[2];    // [NN1, F]
    const float* y    = (const float*)d_in[3];    // [NE1, F]
    const float* z    = (const float*)d_in[4];    // [NE2, F]
    const float* W1   = (const float*)d_in[5];    // [5, F, F]
    const float* b1   = (const float*)d_in[6];    // [5, F]
    const float* bng1 = (const float*)d_in[7];    // [2, F]
    const float* bnb1 = (const float*)d_in[8];
    const float* W2   = (const float*)d_in[9];
    const float* b2   = (const float*)d_in[10];
    const float* bng2 = (const float*)d_in[11];
    const float* bnb2 = (const float*)d_in[12];

    float* xo = (float*)d_out;                         // [NN1, F]
    float* yo = xo + (long long)NN1 * F;               // [NE1, F]
    float* zo = yo + (long long)NE1 * F;               // [NE2, F]

    Scratch S;
    cudaGetSymbolAddress((void**)&S.P0, g_P0);
    cudaGetSymbolAddress((void**)&S.P1, g_P1);
    cudaGetSymbolAddress((void**)&S.P3, g_P3);
    cudaGetSymbolAddress((void**)&S.P4, g_P4);
    cudaGetSymbolAddress((void**)&S.emsg, g_emsg);
    cudaGetSymbolAddress((void**)&S.h, g_h);
    cudaGetSymbolAddress((void**)&S.deg, g_deg);
    cudaGetSymbolAddress((void**)&S.starts, g_starts);
    cudaGetSymbolAddress((void**)&S.cursor, g_cursor);
    cudaGetSymbolAddress((void**)&S.elist, g_elist);
    cudaGetSymbolAddress((void**)&S.bsum, g_bsum);
    cudaGetSymbolAddress((void**)&S.statsE, g_statsE);
    cudaGetSymbolAddress((void**)&S.statsN, g_statsN);
    cudaGetSymbolAddress((void**)&S.scaleE, g_scaleE);
    cudaGetSymbolAddress((void**)&S.shiftE, g_shiftE);
    cudaGetSymbolAddress((void**)&S.scaleN, g_scaleN);
    cudaGetSymbolAddress((void**)&S.shiftN, g_shiftN);

    cudaFuncSetAttribute(gemm_nt_bias,
                         cudaFuncAttributeMaxDynamicSharedMemorySize,
                         (16384 + 2048) * sizeof(float));

    // conv1: node_update on g.  (x_out, m) — m goes into the y-output slot.
    run_conv(S, gidx, gidx + NE1, NN1, NE1, x, y, W1, b1, bng1, bnb1,
             /*node_res=*/x, /*node_out=*/xo, /*edge_res=*/y, /*edge_out=*/yo);
    // conv2: edge_update on line graph. nodes = m (yo), edges = z.
    run_conv(S, lidx, lidx + NE2, NE1, NE2, yo, z, W2, b2, bng2, bnb2,
             /*node_res=*/yo, /*node_out=*/yo, /*edge_res=*/z, /*edge_out=*/zo);
}

// round 3
// speedup vs baseline: 2.0472x; 2.0472x over previous
#include <cuda_runtime.h>
#include <cuda_bf16.h>
#include <cstdint>

#define F 128
static const int NN1 = 50000;   // nodes in g
static const int NE1 = 400000;  // edges in g == nodes of line graph
static const int NE2 = 800000;  // edges in line graph
#define MAXN 400000
#define MAXE 800000

// ---------------- scratch (device globals: no cudaMalloc allowed) ----------
__device__ float  g_P[(size_t)MAXN * 512];       // [row][slot(4)][128] fused projections
__device__ float  g_emsg[(size_t)MAXE * F];
__device__ float  g_h[(size_t)MAXN * F];
__device__ int    g_deg[MAXN];
__device__ int    g_starts[MAXN + 1];
__device__ int    g_cursor[MAXN];
__device__ int    g_elist[MAXE];
__device__ int    g_bsum[1024];
__device__ double g_statsE[256];
__device__ double g_statsN[256];
__device__ float  g_scaleE[F], g_shiftE[F], g_scaleN[F], g_shiftN[F];
__device__ __nv_bfloat16 g_Whi[2 * 5 * 16384];   // swizzled bf16 weight images
__device__ __nv_bfloat16 g_Wlo[2 * 5 * 16384];
__device__ float  g_biasR[2 * 5 * 128];

__device__ __forceinline__ float sigm(float v) { return 1.0f / (1.0f + __expf(-v)); }

__device__ __forceinline__ uint32_t smem_to_u32(const void* p) {
    uint32_t a;
    asm("{ .reg .u64 t; cvta.to.shared.u64 t, %1; cvt.u32.u64 %0, t; }"
        : "=r"(a) : "l"(p));
    return a;
}
__device__ __forceinline__ void cp16(uint32_t dst, const void* src) {
    asm volatile("cp.async.cg.shared.global [%0], [%1], 16;"
                 :: "r"(dst), "l"(src));
}
#define CP_COMMIT() asm volatile("cp.async.commit_group;")
#define CP_WAIT0()  asm volatile("cp.async.wait_group 0;")

#define LDSM_X4(r0, r1, r2, r3, a) \
    asm volatile("ldmatrix.sync.aligned.m8n8.x4.shared.b16 {%0,%1,%2,%3}, [%4];" \
                 : "=r"(r0), "=r"(r1), "=r"(r2), "=r"(r3) : "r"(a))
#define LDSM_X2(r0, r1, a) \
    asm volatile("ldmatrix.sync.aligned.m8n8.x2.shared.b16 {%0,%1}, [%2];" \
                 : "=r"(r0), "=r"(r1) : "r"(a))
#define MMA_BF16(d, a0, a1, a2, a3, b0, b1) \
    asm volatile("mma.sync.aligned.m16n8k16.row.col.f32.bf16.bf16.f32 " \
                 "{%0,%1,%2,%3},{%4,%5,%6,%7},{%8,%9},{%0,%1,%2,%3};" \
                 : "+f"((d)[0]), "+f"((d)[1]), "+f"((d)[2]), "+f"((d)[3]) \
                 : "r"(a0), "r"(a1), "r"(a2), "r"(a3), "r"(b0), "r"(b1))

// XOR-swizzled 128x128 bf16 image: row r, col k; 16B chunks xor'ed by (r&7).
__device__ __host__ __forceinline__ uint32_t sw_byte(int r, int k) {
    return (uint32_t)r * 256u + (uint32_t)(((k >> 3) ^ (r & 7)) << 4)
         + (uint32_t)((k & 7) << 1);
}

// ==================== weight prep: fp32 -> bf16 hi/lo swizzled images =======
__global__ void prep_weights(const float* __restrict__ W1, const float* __restrict__ b1,
                             const float* __restrict__ W2, const float* __restrict__ b2,
                             __nv_bfloat16* __restrict__ Whi,
                             __nv_bfloat16* __restrict__ Wlo,
                             float* __restrict__ biasR)
{
    int idx = blockIdx.x * blockDim.x + threadIdx.x;
    if (idx >= 2 * 5 * 16384) return;
    int c = idx / (5 * 16384);
    int rem = idx % (5 * 16384);
    int s = rem / 16384;
    int e = rem & 16383;
    int n = e >> 7, k = e & 127;
    const int map[5] = {0, 1, 3, 4, 2};   // slots: src_gate,dst_gate,src_upd,dst_upd | edge_gate
    const float* W = (c == 0 ? W1 : W2) + (size_t)map[s] * 16384;
    float a = W[n * 128 + k];
    __nv_bfloat16 h = __float2bfloat16(a);
    __nv_bfloat16 l = __float2bfloat16(a - __bfloat162float(h));
    uint32_t off = sw_byte(n, k) >> 1;
    size_t base = (size_t)(c * 5 + s) * 16384;
    Whi[base + off] = h;
    Wlo[base + off] = l;
    if (e < 128) {
        const float* b = (c == 0 ? b1 : b2);
        biasR[(c * 5 + s) * 128 + e] = b[map[s] * 128 + e];
    }
}

// ==================== HMMA GEMM: out[r, s*128+c] = A[r] @ W_s^T + b_s =======
// A fp32 [R,128]; per slot s: D(128x128) via 3xBF16 split on mma.m16n8k16.
static constexpr int GEMM_SMEM = 196608;   // A hi/lo 64KB + 2 x W hi/lo 64KB

__global__ void __launch_bounds__(256, 1) gemm_mma(
    const float* __restrict__ A, int R,
    const __nv_bfloat16* __restrict__ Whi, const __nv_bfloat16* __restrict__ Wlo,
    const float* __restrict__ biasR, int nW,
    float* __restrict__ out, int outStride)
{
    extern __shared__ char smem[];
    const uint32_t sb   = smem_to_u32(smem);
    const uint32_t A_HI = sb, A_LO = sb + 32768;
    const uint32_t WB   = sb + 65536;            // 2 buffers x (hi 32KB + lo 32KB)
    const int tid = threadIdx.x, lane = tid & 31, wid = tid >> 5;
    const int warpM = wid & 1, warpN = wid >> 1; // warp tile 64m x 32n
    const int rowBase = blockIdx.x * 128;

    // prefetch W slot 0 (overlaps with A load/convert)
    {
        const float4* sh = (const float4*)Whi;
        const float4* sl = (const float4*)Wlo;
        #pragma unroll
        for (int u = 0; u < 8; u++) {
            int i = tid + u * 256;
            cp16(WB + (uint32_t)i * 16, sh + i);
            cp16(WB + 32768 + (uint32_t)i * 16, sl + i);
        }
        CP_COMMIT();
    }

    // load + split A tile into hi/lo swizzled smem
    #pragma unroll
    for (int u = 0; u < 16; u++) {
        int idx = tid + u * 256;          // 0..4095 float4s
        int r = idx >> 5, q = idx & 31;   // row, k-float4
        float4 a = make_float4(0.f, 0.f, 0.f, 0.f);
        if (rowBase + r < R)
            a = ((const float4*)(A + (size_t)(rowBase + r) * 128))[q];
        __nv_bfloat16 h0 = __float2bfloat16(a.x), h1 = __float2bfloat16(a.y);
        __nv_bfloat16 h2 = __float2bfloat16(a.z), h3 = __float2bfloat16(a.w);
        __nv_bfloat162 hp0 = __nv_bfloat162(h0, h1), hp1 = __nv_bfloat162(h2, h3);
        __nv_bfloat162 lp0 = __nv_bfloat162(
            __float2bfloat16(a.x - __bfloat162float(h0)),
            __float2bfloat16(a.y - __bfloat162float(h1)));
        __nv_bfloat162 lp1 = __nv_bfloat162(
            __float2bfloat16(a.z - __bfloat162float(h2)),
            __float2bfloat16(a.w - __bfloat162float(h3)));
        uint32_t off = (uint32_t)r * 256 + (uint32_t)((((q >> 1)) ^ (r & 7)) << 4)
                     + (uint32_t)((q & 1) << 3);
        uint2 hv, lv;
        hv.x = *(uint32_t*)&hp0; hv.y = *(uint32_t*)&hp1;
        lv.x = *(uint32_t*)&lp0; lv.y = *(uint32_t*)&lp1;
        *(uint2*)(smem + off)         = hv;
        *(uint2*)(smem + 32768 + off) = lv;
    }

    // per-lane ldmatrix address components
    const int gA  = lane >> 3;                       // 0..3
    const int rA  = (lane & 7) + ((gA & 1) << 3);    // row within m16 tile
    const int kcA = gA >> 1;                         // kchunk offset 0/1
    const int rB  = lane & 7;
    const int kcB = (lane >> 3) & 1;

    for (int s = 0; s < nW; s++) {
        const uint32_t wb = WB + (uint32_t)(s & 1) * 65536;
        if (s == 0) { CP_WAIT0(); __syncthreads(); }
        if (s + 1 < nW) {  // prefetch next W into other buffer
            const float4* sh = (const float4*)(Whi + (size_t)(s + 1) * 16384);
            const float4* sl = (const float4*)(Wlo + (size_t)(s + 1) * 16384);
            uint32_t dst = WB + (uint32_t)((s + 1) & 1) * 65536;
            #pragma unroll
            for (int u = 0; u < 8; u++) {
                int i = tid + u * 256;
                cp16(dst + (uint32_t)i * 16, sh + i);
                cp16(dst + 32768 + (uint32_t)i * 16, sl + i);
            }
            CP_COMMIT();
        }

        float acc[4][4][4];
        #pragma unroll
        for (int mt = 0; mt < 4; mt++)
            #pragma unroll
            for (int nt = 0; nt < 4; nt++)
                #pragma unroll
                for (int i = 0; i < 4; i++) acc[mt][nt][i] = 0.f;

        #pragma unroll
        for (int ks = 0; ks < 8; ks++) {
            uint32_t ah[4][4], al[4][4], bh[4][2], bl[4][2];
            #pragma unroll
            for (int mt = 0; mt < 4; mt++) {
                int row = warpM * 64 + mt * 16 + rA;
                int kc  = ks * 2 + kcA;
                uint32_t off = (uint32_t)row * 256 + (uint32_t)((kc ^ (row & 7)) << 4);
                LDSM_X4(ah[mt][0], ah[mt][1], ah[mt][2], ah[mt][3], A_HI + off);
                LDSM_X4(al[mt][0], al[mt][1], al[mt][2], al[mt][3], A_LO + off);
            }
            #pragma unroll
            for (int nt = 0; nt < 4; nt++) {
                int row = warpN * 32 + nt * 8 + rB;
                int kc  = ks * 2 + kcB;
                uint32_t off = (uint32_t)row * 256 + (uint32_t)((kc ^ (row & 7)) << 4);
                LDSM_X2(bh[nt][0], bh[nt][1], wb + off);
                LDSM_X2(bl[nt][0], bl[nt][1], wb + 32768 + off);
            }
            #pragma unroll
            for (int mt = 0; mt < 4; mt++)
                #pragma unroll
                for (int nt = 0; nt < 4; nt++) {
                    MMA_BF16(acc[mt][nt], ah[mt][0], ah[mt][1], ah[mt][2], ah[mt][3],
                             bh[nt][0], bh[nt][1]);
                    MMA_BF16(acc[mt][nt], ah[mt][0], ah[mt][1], ah[mt][2], ah[mt][3],
                             bl[nt][0], bl[nt][1]);
                    MMA_BF16(acc[mt][nt], al[mt][0], al[mt][1], al[mt][2], al[mt][3],
                             bh[nt][0], bh[nt][1]);
                }
        }

        // epilogue: bias + store
        #pragma unroll
        for (int mt = 0; mt < 4; mt++) {
            int row0 = rowBase + warpM * 64 + mt * 16 + (lane >> 2);
            #pragma unroll
            for (int nt = 0; nt < 4; nt++) {
                int c = warpN * 32 + nt * 8 + ((lane & 3) << 1);
                float bx = __ldg(biasR + s * 128 + c);
                float by = __ldg(biasR + s * 128 + c + 1);
                if (row0 < R) {
                    float2 v = make_float2(acc[mt][nt][0] + bx, acc[mt][nt][1] + by);
                    *(float2*)(out + (size_t)row0 * outStride + s * 128 + c) = v;
                }
                if (row0 + 8 < R) {
                    float2 v = make_float2(acc[mt][nt][2] + bx, acc[mt][nt][3] + by);
                    *(float2*)(out + (size_t)(row0 + 8) * outStride + s * 128 + c) = v;
                }
            }
        }
        if (s + 1 < nW) { CP_WAIT0(); __syncthreads(); }
    }
}

// ---------------- CSR build ------------------------------------------------
__global__ void hist_deg(const int* __restrict__ ei, int* __restrict__ deg, int E)
{
    for (int e = blockIdx.x * blockDim.x + threadIdx.x; e < E;
         e += gridDim.x * blockDim.x)
        atomicAdd(&deg[ei[e]], 1);
}

__global__ void scan1(const int* __restrict__ in, int* __restrict__ out,
                      int* __restrict__ bsum, int n)
{
    __shared__ int s[1024];
    int i = blockIdx.x * 1024 + threadIdx.x;
    int v = (i < n) ? in[i] : 0;
    s[threadIdx.x] = v;
    __syncthreads();
    for (int off = 1; off < 1024; off <<= 1) {
        int t = (threadIdx.x >= off) ? s[threadIdx.x - off] : 0;
        __syncthreads();
        s[threadIdx.x] += t;
        __syncthreads();
    }
    if (i < n) out[i] = s[threadIdx.x] - v;
    if (threadIdx.x == 1023) bsum[blockIdx.x] = s[1023];
}

__global__ void scan2(int* __restrict__ bsum, int nb)
{
    __shared__ int s[1024];
    int v = (threadIdx.x < nb) ? bsum[threadIdx.x] : 0;
    s[threadIdx.x] = v;
    __syncthreads();
    for (int off = 1; off < 1024; off <<= 1) {
        int t = (threadIdx.x >= off) ? s[threadIdx.x - off] : 0;
        __syncthreads();
        s[threadIdx.x] += t;
        __syncthreads();
    }
    if (threadIdx.x < nb) bsum[threadIdx.x] = s[threadIdx.x] - v;
}

__global__ void scan3(int* __restrict__ out, const int* __restrict__ bsum,
                      int n, int total)
{
    int i = blockIdx.x * 1024 + threadIdx.x;
    if (i < n) out[i] += bsum[blockIdx.x];
    if (blockIdx.x == 0 && threadIdx.x == 0) out[n] = total;
}

__global__ void scatter_edges(const int* __restrict__ ei,
                              const int* __restrict__ starts,
                              int* __restrict__ cursor, int* __restrict__ elist, int E)
{
    for (int e = blockIdx.x * blockDim.x + threadIdx.x; e < E;
         e += gridDim.x * blockDim.x) {
        int n = ei[e];
        int p = atomicAdd(&cursor[n], 1);
        elist[starts[n] + p] = e;
    }
}

// ------- edge pass: emsg += P0[i] + P1[j]; accumulate BN stats --------------
__global__ void __launch_bounds__(256) edge_pass(
    const int* __restrict__ ei, const int* __restrict__ ej,
    const float* __restrict__ P,
    float* __restrict__ emsg, int E, double* __restrict__ stats)
{
    __shared__ float ssum[128], ssq[128];
    if (threadIdx.x < 128) { ssum[threadIdx.x] = 0.f; ssq[threadIdx.x] = 0.f; }
    __syncthreads();
    const int lane = threadIdx.x & 31;
    float4 ls = make_float4(0.f, 0.f, 0.f, 0.f);
    float4 lq = make_float4(0.f, 0.f, 0.f, 0.f);
    const long long total = (long long)E * 32;
    for (long long idx = (long long)blockIdx.x * blockDim.x + threadIdx.x;
         idx < total; idx += (long long)gridDim.x * blockDim.x) {
        int e = (int)(idx >> 5);
        int i = ei[e], j = ej[e];
        float4 v  = ((const float4*)emsg)[idx];
        float4 p0 = ((const float4*)P)[(long long)i * 128 + lane];
        float4 p1 = ((const float4*)P)[(long long)j * 128 + 32 + lane];
        v.x += p0.x + p1.x; v.y += p0.y + p1.y;
        v.z += p0.z + p1.z; v.w += p0.w + p1.w;
        ((float4*)emsg)[idx] = v;
        ls.x += v.x; ls.y += v.y; ls.z += v.z; ls.w += v.w;
        lq.x += v.x * v.x; lq.y += v.y * v.y; lq.z += v.z * v.z; lq.w += v.w * v.w;
    }
    atomicAdd(&ssum[lane * 4 + 0], ls.x); atomicAdd(&ssum[lane * 4 + 1], ls.y);
    atomicAdd(&ssum[lane * 4 + 2], ls.z); atomicAdd(&ssum[lane * 4 + 3], ls.w);
    atomicAdd(&ssq[lane * 4 + 0], lq.x);  atomicAdd(&ssq[lane * 4 + 1], lq.y);
    atomicAdd(&ssq[lane * 4 + 2], lq.z);  atomicAdd(&ssq[lane * 4 + 3], lq.w);
    __syncthreads();
    if (threadIdx.x < 128) {
        atomicAdd(&stats[threadIdx.x],       (double)ssum[threadIdx.x]);
        atomicAdd(&stats[128 + threadIdx.x], (double)ssq[threadIdx.x]);
    }
}

// ------- per-node aggregation (warp per node, CSR gather) -------------------
__global__ void __launch_bounds__(256) node_agg(
    const int* __restrict__ starts, const int* __restrict__ elist,
    const int* __restrict__ ej, const float* __restrict__ emsg,
    const float* __restrict__ P,
    float* __restrict__ h, int nN, double* __restrict__ stats)
{
    __shared__ float ssum[128], ssq[128];
    if (threadIdx.x < 128) { ssum[threadIdx.x] = 0.f; ssq[threadIdx.x] = 0.f; }
    __syncthreads();
    const int lane  = threadIdx.x & 31;
    const int warp  = (blockIdx.x * blockDim.x + threadIdx.x) >> 5;
    const int nwarp = (gridDim.x * blockDim.x) >> 5;
    float4 ls = make_float4(0.f, 0.f, 0.f, 0.f);
    float4 lq = make_float4(0.f, 0.f, 0.f, 0.f);
    for (int n = warp; n < nN; n += nwarp) {
        int s = starts[n], t = starts[n + 1];
        float4 sg = make_float4(0.f, 0.f, 0.f, 0.f);
        float4 sn = make_float4(0.f, 0.f, 0.f, 0.f);
        for (int k = s; k < t; k++) {
            int e = elist[k];
            int j = ej[e];
            float4 v  = ((const float4*)emsg)[(long long)e * 32 + lane];
            float4 sig = make_float4(sigm(v.x), sigm(v.y), sigm(v.z), sigm(v.w));
            float4 p4 = ((const float4*)P)[(long long)j * 128 + 96 + lane];
            sg.x += sig.x; sg.y += sig.y; sg.z += sig.z; sg.w += sig.w;
            sn.x += sig.x * p4.x; sn.y += sig.y * p4.y;
            sn.z += sig.z * p4.z; sn.w += sig.w * p4.w;
        }
        float4 hv = ((const float4*)P)[(long long)n * 128 + 64 + lane];
        hv.x += sn.x / (sg.x + 1e-9f); hv.y += sn.y / (sg.y + 1e-9f);
        hv.z += sn.z / (sg.z + 1e-9f); hv.w += sn.w / (sg.w + 1e-9f);
        ((float4*)h)[(long long)n * 32 + lane] = hv;
        ls.x += hv.x; ls.y += hv.y; ls.z += hv.z; ls.w += hv.w;
        lq.x += hv.x * hv.x; lq.y += hv.y * hv.y;
        lq.z += hv.z * hv.z; lq.w += hv.w * hv.w;
    }
    atomicAdd(&ssum[lane * 4 + 0], ls.x); atomicAdd(&ssum[lane * 4 + 1], ls.y);
    atomicAdd(&ssum[lane * 4 + 2], ls.z); atomicAdd(&ssum[lane * 4 + 3], ls.w);
    atomicAdd(&ssq[lane * 4 + 0], lq.x);  atomicAdd(&ssq[lane * 4 + 1], lq.y);
    atomicAdd(&ssq[lane * 4 + 2], lq.z);  atomicAdd(&ssq[lane * 4 + 3], lq.w);
    __syncthreads();
    if (threadIdx.x < 128) {
        atomicAdd(&stats[threadIdx.x],       (double)ssum[threadIdx.x]);
        atomicAdd(&stats[128 + threadIdx.x], (double)ssq[threadIdx.x]);
    }
}

// ---------------- BN finalize + fused apply ---------------------------------
__global__ void finalize_bn(const double* __restrict__ stats,
                            const float* __restrict__ gamma,
                            const float* __restrict__ beta,
                            double invR, float* __restrict__ scale,
                            float* __restrict__ shift)
{
    int f = threadIdx.x;
    double mu  = stats[f] * invR;
    double var = stats[128 + f] * invR - mu * mu;
    float inv = rsqrtf((float)var + 1e-5f);
    float s = gamma[f] * inv;
    scale[f] = s;
    shift[f] = beta[f] - s * (float)mu;
}

__global__ void apply_bn_silu_res(const float* __restrict__ hbuf,
                                  const float* __restrict__ res,
                                  const float* __restrict__ scale,
                                  const float* __restrict__ shift,
                                  float* __restrict__ out, long long n4)
{
    for (long long idx = (long long)blockIdx.x * blockDim.x + threadIdx.x;
         idx < n4; idx += (long long)gridDim.x * blockDim.x) {
        int l = (int)(idx & 31);
        float4 sc = ((const float4*)scale)[l];
        float4 sh = ((const float4*)shift)[l];
        float4 v = ((const float4*)hbuf)[idx];
        v.x = v.x * sc.x + sh.x; v.y = v.y * sc.y + sh.y;
        v.z = v.z * sc.z + sh.z; v.w = v.w * sc.w + sh.w;
        float4 u = make_float4(v.x * sigm(v.x), v.y * sigm(v.y),
                               v.z * sigm(v.z), v.w * sigm(v.w));
        float4 r = ((const float4*)res)[idx];
        u.x += r.x; u.y += r.y; u.z += r.z; u.w += r.w;
        ((float4*)out)[idx] = u;
    }
}

// ---------------- host orchestration ----------------------------------------
struct Scratch {
    float *P, *emsg, *h;
    int *deg, *starts, *cursor, *elist, *bsum;
    double *statsE, *statsN;
    float *scaleE, *shiftE, *scaleN, *shiftN;
    __nv_bfloat16 *Whi, *Wlo;
    float *biasR;
};

static void run_conv(const Scratch& S, int conv,
                     const int* ei, const int* ej, int nN, int E,
                     const float* xnode, const float* eedge,
                     const float* bng, const float* bnb,
                     const float* node_res, float* node_out,
                     const float* edge_res, float* edge_out)
{
    cudaStream_t st = 0;
    cudaMemsetAsync(S.deg, 0, (size_t)nN * sizeof(int), st);
    cudaMemsetAsync(S.cursor, 0, (size_t)nN * sizeof(int), st);
    cudaMemsetAsync(S.statsE, 0, 256 * sizeof(double), st);
    cudaMemsetAsync(S.statsN, 0, 256 * sizeof(double), st);

    int gbN = (nN + 127) / 128;
    int gbE = (E + 127) / 128;
    const __nv_bfloat16* Whi = S.Whi + (size_t)conv * 5 * 16384;
    const __nv_bfloat16* Wlo = S.Wlo + (size_t)conv * 5 * 16384;
    const float* biasR = S.biasR + conv * 5 * 128;

    // fused node projections (slots 0..3 -> P), edge projection (slot 4 -> emsg)
    gemm_mma<<<gbN, 256, GEMM_SMEM, st>>>(xnode, nN, Whi, Wlo, biasR, 4, S.P, 512);
    gemm_mma<<<gbE, 256, GEMM_SMEM, st>>>(eedge, E, Whi + 4 * 16384, Wlo + 4 * 16384,
                                          biasR + 4 * 128, 1, S.emsg, 128);

    // CSR
    hist_deg<<<2048, 256, 0, st>>>(ei, S.deg, E);
    int nb = (nN + 1023) / 1024;
    scan1<<<nb, 1024, 0, st>>>(S.deg, S.starts, S.bsum, nN);
    scan2<<<1, 1024, 0, st>>>(S.bsum, nb);
    scan3<<<nb, 1024, 0, st>>>(S.starts, S.bsum, nN, E);
    scatter_edges<<<2048, 256, 0, st>>>(ei, S.starts, S.cursor, S.elist, E);

    edge_pass<<<4096, 256, 0, st>>>(ei, ej, S.P, S.emsg, E, S.statsE);
    finalize_bn<<<1, 128, 0, st>>>(S.statsE, bng + 0 * 128, bnb + 0 * 128,
                                   1.0 / (double)E, S.scaleE, S.shiftE);

    node_agg<<<4096, 256, 0, st>>>(S.starts, S.elist, ej, S.emsg, S.P,
                                   S.h, nN, S.statsN);
    finalize_bn<<<1, 128, 0, st>>>(S.statsN, bng + 1 * 128, bnb + 1 * 128,
                                   1.0 / (double)nN, S.scaleN, S.shiftN);

    long long n4n = (long long)nN * 32;
    long long n4e = (long long)E * 32;
    int gbA = (int)((n4n + 255) / 256); if (gbA > 8192) gbA = 8192;
    int gbB = (int)((n4e + 255) / 256); if (gbB > 8192) gbB = 8192;
    apply_bn_silu_res<<<gbA, 256, 0, st>>>(S.h, node_res, S.scaleN, S.shiftN,
                                           node_out, n4n);
    apply_bn_silu_res<<<gbB, 256, 0, st>>>(S.emsg, edge_res, S.scaleE, S.shiftE,
                                           edge_out, n4e);
}

extern "C" void kernel_launch(void* const* d_in, const int* in_sizes, int n_in,
                              void* d_out, int out_size)
{
    const int*   gidx = (const int*)d_in[0];
    const int*   lidx = (const int*)d_in[1];
    const float* x    = (const float*)d_in[2];
    const float* y    = (const float*)d_in[3];
    const float* z    = (const float*)d_in[4];
    const float* W1   = (const float*)d_in[5];
    const float* b1   = (const float*)d_in[6];
    const float* bng1 = (const float*)d_in[7];
    const float* bnb1 = (const float*)d_in[8];
    const float* W2   = (const float*)d_in[9];
    const float* b2   = (const float*)d_in[10];
    const float* bng2 = (const float*)d_in[11];
    const float* bnb2 = (const float*)d_in[12];

    float* xo = (float*)d_out;
    float* yo = xo + (long long)NN1 * F;
    float* zo = yo + (long long)NE1 * F;

    Scratch S;
    cudaGetSymbolAddress((void**)&S.P, g_P);
    cudaGetSymbolAddress((void**)&S.emsg, g_emsg);
    cudaGetSymbolAddress((void**)&S.h, g_h);
    cudaGetSymbolAddress((void**)&S.deg, g_deg);
    cudaGetSymbolAddress((void**)&S.starts, g_starts);
    cudaGetSymbolAddress((void**)&S.cursor, g_cursor);
    cudaGetSymbolAddress((void**)&S.elist, g_elist);
    cudaGetSymbolAddress((void**)&S.bsum, g_bsum);
    cudaGetSymbolAddress((void**)&S.statsE, g_statsE);
    cudaGetSymbolAddress((void**)&S.statsN, g_statsN);
    cudaGetSymbolAddress((void**)&S.scaleE, g_scaleE);
    cudaGetSymbolAddress((void**)&S.shiftE, g_shiftE);
    cudaGetSymbolAddress((void**)&S.scaleN, g_scaleN);
    cudaGetSymbolAddress((void**)&S.shiftN, g_shiftN);
    cudaGetSymbolAddress((void**)&S.Whi, g_Whi);
    cudaGetSymbolAddress((void**)&S.Wlo, g_Wlo);
    cudaGetSymbolAddress((void**)&S.biasR, g_biasR);

    cudaFuncSetAttribute(gemm_mma, cudaFuncAttributeMaxDynamicSharedMemorySize,
                         GEMM_SMEM);

    prep_weights<<<(2 * 5 * 16384 + 255) / 256, 256>>>(W1, b1, W2, b2,
                                                       S.Whi, S.Wlo, S.biasR);

    // conv1: node_update on g
    run_conv(S, 0, gidx, gidx + NE1, NN1, NE1, x, y, bng1, bnb1,
             /*node_res=*/x, /*node_out=*/xo, /*edge_res=*/y, /*edge_out=*/yo);
    // conv2: edge_update on line graph (nodes = m = yo, edges = z)
    run_conv(S, 1, lidx, lidx + NE2, NE1, NE2, yo, z, bng2, bnb2,
             /*node_res=*/yo, /*node_out=*/yo, /*edge_res=*/z, /*edge_out=*/zo);
}